// round 1
// baseline (speedup 1.0000x reference)
#include <cuda_runtime.h>
#include <math.h>

#define HD   128      // H*D
#define NH   8        // heads
#define DH   16       // dim per head
#define MAXN 50000

// Scratch (device globals: allocation-free per harness rules)
__device__ float g_Q[MAXN * HD];
__device__ float g_K[MAXN * HD];
__device__ float g_V[MAXN * HD];
__device__ float g_z[MAXN * NH];

// ---------------------------------------------------------------------------
// Init: zero output accumulator and z
// ---------------------------------------------------------------------------
__global__ void init_kernel(float* __restrict__ out, int n) {
    int total = n * HD;
    for (int i = blockIdx.x * blockDim.x + threadIdx.x; i < total;
         i += gridDim.x * blockDim.x)
        out[i] = 0.0f;
    int totalz = n * NH;
    for (int i = blockIdx.x * blockDim.x + threadIdx.x; i < totalz;
         i += gridDim.x * blockDim.x)
        g_z[i] = 0.0f;
}

// ---------------------------------------------------------------------------
// Fused QKV projection GEMM: out_m = h @ W_m + b_m  (m = blockIdx.y in {Q,K,V})
// Tiled fp32: TM=64 rows, TN=128 cols (full width), TK=32.
// 256 threads, each computes 4 rows x 8 cols.
// ---------------------------------------------------------------------------
#define TM 64
#define TN 128
#define TK 32

__global__ void qkv_gemm(const float* __restrict__ h,
                         const float* __restrict__ Wq, const float* __restrict__ bq,
                         const float* __restrict__ Wk, const float* __restrict__ bk,
                         const float* __restrict__ Wv, const float* __restrict__ bv,
                         int n) {
    const int m = blockIdx.y;
    const float* W    = (m == 0) ? Wq : (m == 1) ? Wk : Wv;
    const float* bias = (m == 0) ? bq : (m == 1) ? bk : bv;
    float* out        = (m == 0) ? g_Q : (m == 1) ? g_K : g_V;

    __shared__ float hs[TK][TM + 4];   // transposed: hs[k][row]
    __shared__ float ws[TK][TN + 4];   // ws[k][col]

    const int tid = threadIdx.x;
    const int ty  = tid / 16;          // 0..15 -> row group (4 rows)
    const int tx  = tid % 16;          // 0..15 -> col group (8 cols)
    const int rowBase = blockIdx.x * TM;

    float acc[4][8];
#pragma unroll
    for (int i = 0; i < 4; i++)
#pragma unroll
        for (int j = 0; j < 8; j++) acc[i][j] = 0.0f;

    for (int kb = 0; kb < HD / TK; kb++) {
        // load h tile (transposed into shared)
        for (int idx = tid; idx < TM * TK / 4; idx += 256) {
            int r  = idx / 8;       // row in tile
            int kq = idx % 8;       // k-quad
            int grow = rowBase + r;
            float4 v = make_float4(0.f, 0.f, 0.f, 0.f);
            if (grow < n)
                v = *(const float4*)&h[(size_t)grow * HD + kb * TK + kq * 4];
            hs[kq * 4 + 0][r] = v.x;
            hs[kq * 4 + 1][r] = v.y;
            hs[kq * 4 + 2][r] = v.z;
            hs[kq * 4 + 3][r] = v.w;
        }
        // load W tile
        for (int idx = tid; idx < TK * TN / 4; idx += 256) {
            int k  = idx / 32;
            int cq = idx % 32;
            float4 v = *(const float4*)&W[(size_t)(kb * TK + k) * HD + cq * 4];
            *(float4*)&ws[k][cq * 4] = v;
        }
        __syncthreads();

#pragma unroll
        for (int k = 0; k < TK; k++) {
            float4 a  = *(float4*)&hs[k][ty * 4];
            float4 b0 = *(float4*)&ws[k][tx * 8];
            float4 b1 = *(float4*)&ws[k][tx * 8 + 4];
            float av[4] = {a.x, a.y, a.z, a.w};
            float bv8[8] = {b0.x, b0.y, b0.z, b0.w, b1.x, b1.y, b1.z, b1.w};
#pragma unroll
            for (int i = 0; i < 4; i++)
#pragma unroll
                for (int j = 0; j < 8; j++) acc[i][j] += av[i] * bv8[j];
        }
        __syncthreads();
    }

    // epilogue: add bias, store
    float bcol[8];
#pragma unroll
    for (int j = 0; j < 8; j++) bcol[j] = bias[tx * 8 + j];

#pragma unroll
    for (int i = 0; i < 4; i++) {
        int grow = rowBase + ty * 4 + i;
        if (grow < n) {
            float4 o0 = make_float4(acc[i][0] + bcol[0], acc[i][1] + bcol[1],
                                    acc[i][2] + bcol[2], acc[i][3] + bcol[3]);
            float4 o1 = make_float4(acc[i][4] + bcol[4], acc[i][5] + bcol[5],
                                    acc[i][6] + bcol[6], acc[i][7] + bcol[7]);
            *(float4*)&out[(size_t)grow * HD + tx * 8]     = o0;
            *(float4*)&out[(size_t)grow * HD + tx * 8 + 4] = o1;
        }
    }
}

// ---------------------------------------------------------------------------
// Edge kernel: one warp per edge.
// Lane l owns floats [4l, 4l+4) of the 128-wide row -> head = l>>2.
// score_h = exp(clip(dot(K[src],Q[dst])_h / 4, -5, 5))
// out[dst] += V[src]*score ; z[dst] += score
// ---------------------------------------------------------------------------
__global__ void edge_kernel(const int* __restrict__ src,
                            const int* __restrict__ dst,
                            float* __restrict__ out, int E) {
    int e = (blockIdx.x * blockDim.x + threadIdx.x) >> 5;
    if (e >= E) return;
    int lane = threadIdx.x & 31;

    int s = src[e];   // broadcast load (same addr across warp)
    int d = dst[e];

    const float4 k4 = *(const float4*)&g_K[(size_t)s * HD + lane * 4];
    const float4 q4 = *(const float4*)&g_Q[(size_t)d * HD + lane * 4];

    float p = k4.x * q4.x + k4.y * q4.y + k4.z * q4.z + k4.w * q4.w;
    // reduce within the 4-lane head group
    p += __shfl_xor_sync(0xffffffffu, p, 1);
    p += __shfl_xor_sync(0xffffffffu, p, 2);

    float sc = expf(fminf(fmaxf(p * 0.25f, -5.0f), 5.0f));

    const float4 v4 = *(const float4*)&g_V[(size_t)s * HD + lane * 4];
    float* o = out + (size_t)d * HD + lane * 4;

    float a0 = v4.x * sc, a1 = v4.y * sc, a2 = v4.z * sc, a3 = v4.w * sc;
    asm volatile("red.global.add.v4.f32 [%0], {%1,%2,%3,%4};"
                 :: "l"(o), "f"(a0), "f"(a1), "f"(a2), "f"(a3)
                 : "memory");

    if ((lane & 3) == 0)
        atomicAdd(&g_z[(size_t)d * NH + (lane >> 2)], sc);
}

// ---------------------------------------------------------------------------
// Finalize: out = out / (z + 1e-6), float4 grid-stride
// ---------------------------------------------------------------------------
__global__ void finalize_kernel(float* __restrict__ out, int n) {
    int total4 = n * (HD / 4);   // 32 quads per node
    for (int i = blockIdx.x * blockDim.x + threadIdx.x; i < total4;
         i += gridDim.x * blockDim.x) {
        int node = i >> 5;
        int head = (i & 31) >> 2;
        float zz = g_z[(size_t)node * NH + head] + 1e-6f;
        float4 v = ((float4*)out)[i];
        float inv = 1.0f / zz;
        v.x *= inv; v.y *= inv; v.z *= inv; v.w *= inv;
        ((float4*)out)[i] = v;
    }
}

// ---------------------------------------------------------------------------
extern "C" void kernel_launch(void* const* d_in, const int* in_sizes, int n_in,
                              void* d_out, int out_size) {
    const float* h  = (const float*)d_in[0];
    const float* Wq = (const float*)d_in[1];
    const float* bq = (const float*)d_in[2];
    const float* Wk = (const float*)d_in[3];
    const float* bk = (const float*)d_in[4];
    const float* Wv = (const float*)d_in[5];
    const float* bv = (const float*)d_in[6];
    const int*  src = (const int*)d_in[7];
    const int*  dst = (const int*)d_in[8];
    float* out = (float*)d_out;

    const int n = in_sizes[0] / HD;
    const int E = in_sizes[7];

    init_kernel<<<592, 256>>>(out, n);

    dim3 gg((n + TM - 1) / TM, 3);
    qkv_gemm<<<gg, 256>>>(h, Wq, bq, Wk, bk, Wv, bv, n);

    // one warp per edge, 8 edges per 256-thread block
    edge_kernel<<<(E + 7) / 8, 256>>>(src, dst, out, E);

    finalize_kernel<<<592, 256>>>(out, n);
}

// round 2
// speedup vs baseline: 1.1338x; 1.1338x over previous
#include <cuda_runtime.h>
#include <math.h>

#define HD    128       // H*D
#define NH    8         // heads
#define MAXN  50000
#define MAXE  1600000

// Scratch (device globals: allocation-free per harness rules)
__device__ float g_Q[MAXN * HD];
__device__ float g_K[MAXN * HD];
__device__ float g_V[MAXN * HD];

// CSR sort scratch
__device__ int g_cnt[MAXN];
__device__ int g_off[MAXN + 1];
__device__ int g_pos[MAXN];
__device__ int g_esrc[MAXE];

// ---------------------------------------------------------------------------
// Counting sort by dst: zero -> histogram -> scan -> scatter
// ---------------------------------------------------------------------------
__global__ void zero_cnt_kernel(int n) {
    int i = blockIdx.x * blockDim.x + threadIdx.x;
    if (i < n) g_cnt[i] = 0;
}

__global__ void hist_kernel(const int* __restrict__ dst, int E) {
    for (int i = blockIdx.x * blockDim.x + threadIdx.x; i < E;
         i += gridDim.x * blockDim.x)
        atomicAdd(&g_cnt[dst[i]], 1);
}

#define SCAN_T 1024
__global__ void scan_kernel(int n) {
    __shared__ int ssum[SCAN_T];
    const int tid = threadIdx.x;
    const int per = (n + SCAN_T - 1) / SCAN_T;
    const int start = tid * per;
    const int end   = min(start + per, n);

    int s = 0;
    for (int i = start; i < end; i++) s += g_cnt[i];
    ssum[tid] = s;
    __syncthreads();

    // Hillis-Steele inclusive scan over the 1024 partials
    for (int off = 1; off < SCAN_T; off <<= 1) {
        int t = (tid >= off) ? ssum[tid - off] : 0;
        __syncthreads();
        ssum[tid] += t;
        __syncthreads();
    }

    int run = ssum[tid] - s;  // exclusive base for this thread's chunk
    for (int i = start; i < end; i++) {
        int c = g_cnt[i];
        g_off[i] = run;
        g_pos[i] = run;
        run += c;
    }
    if (tid == SCAN_T - 1) g_off[n] = run;
}

__global__ void scatter_kernel(const int* __restrict__ src,
                               const int* __restrict__ dst, int E) {
    for (int i = blockIdx.x * blockDim.x + threadIdx.x; i < E;
         i += gridDim.x * blockDim.x) {
        int d = dst[i];
        int p = atomicAdd(&g_pos[d], 1);
        g_esrc[p] = src[i];
    }
}

// ---------------------------------------------------------------------------
// Fused QKV projection GEMM: out_m = h @ W_m + b_m  (m = blockIdx.y in {Q,K,V})
// Tiled fp32: TM=64 rows, TN=128 cols (full width), TK=32. 256 threads,
// each computes 4 rows x 8 cols. (unchanged from R1 — FFMA-bound baseline)
// ---------------------------------------------------------------------------
#define TM 64
#define TN 128
#define TK 32

__global__ void qkv_gemm(const float* __restrict__ h,
                         const float* __restrict__ Wq, const float* __restrict__ bq,
                         const float* __restrict__ Wk, const float* __restrict__ bk,
                         const float* __restrict__ Wv, const float* __restrict__ bv,
                         int n) {
    const int m = blockIdx.y;
    const float* W    = (m == 0) ? Wq : (m == 1) ? Wk : Wv;
    const float* bias = (m == 0) ? bq : (m == 1) ? bk : bv;
    float* out        = (m == 0) ? g_Q : (m == 1) ? g_K : g_V;

    __shared__ float hs[TK][TM + 4];
    __shared__ float ws[TK][TN + 4];

    const int tid = threadIdx.x;
    const int ty  = tid / 16;
    const int tx  = tid % 16;
    const int rowBase = blockIdx.x * TM;

    float acc[4][8];
#pragma unroll
    for (int i = 0; i < 4; i++)
#pragma unroll
        for (int j = 0; j < 8; j++) acc[i][j] = 0.0f;

    for (int kb = 0; kb < HD / TK; kb++) {
        for (int idx = tid; idx < TM * TK / 4; idx += 256) {
            int r  = idx / 8;
            int kq = idx % 8;
            int grow = rowBase + r;
            float4 v = make_float4(0.f, 0.f, 0.f, 0.f);
            if (grow < n)
                v = *(const float4*)&h[(size_t)grow * HD + kb * TK + kq * 4];
            hs[kq * 4 + 0][r] = v.x;
            hs[kq * 4 + 1][r] = v.y;
            hs[kq * 4 + 2][r] = v.z;
            hs[kq * 4 + 3][r] = v.w;
        }
        for (int idx = tid; idx < TK * TN / 4; idx += 256) {
            int k  = idx / 32;
            int cq = idx % 32;
            float4 v = *(const float4*)&W[(size_t)(kb * TK + k) * HD + cq * 4];
            *(float4*)&ws[k][cq * 4] = v;
        }
        __syncthreads();

#pragma unroll
        for (int k = 0; k < TK; k++) {
            float4 a  = *(float4*)&hs[k][ty * 4];
            float4 b0 = *(float4*)&ws[k][tx * 8];
            float4 b1 = *(float4*)&ws[k][tx * 8 + 4];
            float av[4] = {a.x, a.y, a.z, a.w};
            float bv8[8] = {b0.x, b0.y, b0.z, b0.w, b1.x, b1.y, b1.z, b1.w};
#pragma unroll
            for (int i = 0; i < 4; i++)
#pragma unroll
                for (int j = 0; j < 8; j++) acc[i][j] += av[i] * bv8[j];
        }
        __syncthreads();
    }

    float bcol[8];
#pragma unroll
    for (int j = 0; j < 8; j++) bcol[j] = bias[tx * 8 + j];

#pragma unroll
    for (int i = 0; i < 4; i++) {
        int grow = rowBase + ty * 4 + i;
        if (grow < n) {
            float4 o0 = make_float4(acc[i][0] + bcol[0], acc[i][1] + bcol[1],
                                    acc[i][2] + bcol[2], acc[i][3] + bcol[3]);
            float4 o1 = make_float4(acc[i][4] + bcol[4], acc[i][5] + bcol[5],
                                    acc[i][6] + bcol[6], acc[i][7] + bcol[7]);
            *(float4*)&out[(size_t)grow * HD + tx * 8]     = o0;
            *(float4*)&out[(size_t)grow * HD + tx * 8 + 4] = o1;
        }
    }
}

// ---------------------------------------------------------------------------
// Gather kernel: one warp per destination node.
// Lane l owns floats [4l, 4l+4) of the 128-wide row; head = l>>2.
// Q[dst] in registers, wV and z accumulate in registers, normalize on write.
// No atomics, no init/finalize passes.
// ---------------------------------------------------------------------------
__global__ void gather_kernel(float* __restrict__ out, int n) {
    int node = (blockIdx.x * blockDim.x + threadIdx.x) >> 5;
    if (node >= n) return;
    const int lane = threadIdx.x & 31;

    const float4 q4 = *(const float4*)&g_Q[(size_t)node * HD + lane * 4];

    float ax = 0.f, ay = 0.f, az = 0.f, aw = 0.f;
    float zacc = 0.f;

    const int beg  = g_off[node];
    const int endo = g_off[node + 1];

    for (int ebase = beg; ebase < endo; ebase += 32) {
        int myे_guard = ebase + lane;
        int my_s = (myे_guard < endo) ? g_esrc[myे_guard] : 0;
        int cnt = endo - ebase;
        if (cnt > 32) cnt = 32;

        for (int j = 0; j < cnt; j++) {
            int s = __shfl_sync(0xffffffffu, my_s, j);

            const float4 k4 = *(const float4*)&g_K[(size_t)s * HD + lane * 4];
            const float4 v4 = *(const float4*)&g_V[(size_t)s * HD + lane * 4];

            float p = k4.x * q4.x + k4.y * q4.y + k4.z * q4.z + k4.w * q4.w;
            p += __shfl_xor_sync(0xffffffffu, p, 1);
            p += __shfl_xor_sync(0xffffffffu, p, 2);

            float sc = __expf(fminf(fmaxf(p * 0.25f, -5.0f), 5.0f));

            ax += v4.x * sc;
            ay += v4.y * sc;
            az += v4.z * sc;
            aw += v4.w * sc;
            zacc += sc;
        }
    }

    float inv = 1.0f / (zacc + 1e-6f);
    float4 o = make_float4(ax * inv, ay * inv, az * inv, aw * inv);
    *(float4*)&out[(size_t)node * HD + lane * 4] = o;
}

// ---------------------------------------------------------------------------
extern "C" void kernel_launch(void* const* d_in, const int* in_sizes, int n_in,
                              void* d_out, int out_size) {
    const float* h  = (const float*)d_in[0];
    const float* Wq = (const float*)d_in[1];
    const float* bq = (const float*)d_in[2];
    const float* Wk = (const float*)d_in[3];
    const float* bk = (const float*)d_in[4];
    const float* Wv = (const float*)d_in[5];
    const float* bv = (const float*)d_in[6];
    const int*  src = (const int*)d_in[7];
    const int*  dst = (const int*)d_in[8];
    float* out = (float*)d_out;

    const int n = in_sizes[0] / HD;
    const int E = in_sizes[7];

    // CSR sort by dst
    zero_cnt_kernel<<<(n + 255) / 256, 256>>>(n);
    hist_kernel<<<2368, 256>>>(dst, E);
    scan_kernel<<<1, SCAN_T>>>(n);
    scatter_kernel<<<2368, 256>>>(src, dst, E);

    // QKV projections
    dim3 gg((n + TM - 1) / TM, 3);
    qkv_gemm<<<gg, 256>>>(h, Wq, bq, Wk, bk, Wv, bv, n);

    // Gather + normalize (one warp per node)
    gather_kernel<<<(n * 32 + 255) / 256, 256>>>(out, n);
}

// round 4
// speedup vs baseline: 1.5063x; 1.3286x over previous
#include <cuda_runtime.h>
#include <cuda_bf16.h>
#include <cuda_fp16.h>
#include <math.h>
#include <cstdint>

#define HD       128
#define MAXN     50000
#define MAXN_PAD 50048            // 782 * 64
#define MAXE     1600000
#define TILES    (MAXN_PAD / 16)  // 3128 (16-row warp tiles)
#define KSTEPS   8

// ---------------------------------------------------------------------------
// Device scratch (allocation-free per harness rules)
// ---------------------------------------------------------------------------
__device__ float  g_Q [MAXN_PAD * HD];
__device__ __half g_Kh[MAXN_PAD * HD];
__device__ __half g_Vh[MAXN_PAD * HD];

// Fragment-major A (bf16 hi/lo): [tile][kstep][lane] -> uint4 (4 b32 = 8 bf16)
__device__ uint4 g_Afrag_hi[TILES * KSTEPS * 32];
__device__ uint4 g_Afrag_lo[TILES * KSTEPS * 32];
// Fragment-major B: [mat][kstep][ntile][lane] -> uint4 {b0hi,b1hi,b0lo,b1lo}
__device__ uint4 g_Bfrag[3 * KSTEPS * 16 * 32];

// CSR sort scratch
__device__ int g_cnt[MAXN];
__device__ int g_off[MAXN + 1];
__device__ int g_pos[MAXN];
__device__ int g_esrc[MAXE];

// ---------------------------------------------------------------------------
// Helpers
// ---------------------------------------------------------------------------
__device__ __forceinline__ void split2(float x, float y, uint32_t& hi, uint32_t& lo) {
    __nv_bfloat16 hx = __float2bfloat16(x);
    __nv_bfloat16 hy = __float2bfloat16(y);
    __nv_bfloat16 lx = __float2bfloat16(x - __bfloat162float(hx));
    __nv_bfloat16 ly = __float2bfloat16(y - __bfloat162float(hy));
    __nv_bfloat162 H(hx, hy), L(lx, ly);
    hi = *(uint32_t*)&H;
    lo = *(uint32_t*)&L;
}

#define MMA16816(c, a0, a1, a2, a3, b0, b1)                                  \
    asm volatile(                                                            \
        "mma.sync.aligned.m16n8k16.row.col.f32.bf16.bf16.f32 "              \
        "{%0,%1,%2,%3}, {%4,%5,%6,%7}, {%8,%9}, {%0,%1,%2,%3};"             \
        : "+f"((c)[0]), "+f"((c)[1]), "+f"((c)[2]), "+f"((c)[3])             \
        : "r"(a0), "r"(a1), "r"(a2), "r"(a3), "r"(b0), "r"(b1))

// ---------------------------------------------------------------------------
// prep_A: h (fp32) -> bf16 hi/lo fragments. One thread per (tile, kstep, lane).
// Fragment layout (mma.m16n8k16 A, row-major):
//   a0: (r = l>>2,   k = (l&3)*2 +{0,1})   a1: (r+8, same k)
//   a2: (r,          k+8 +{0,1})           a3: (r+8, k+8)
// ---------------------------------------------------------------------------
__global__ void prep_A(const float* __restrict__ h, int n) {
    int idx = blockIdx.x * blockDim.x + threadIdx.x;   // grid sized exactly
    int lane = idx & 31;
    int s    = (idx >> 5) & 7;
    int t    = idx >> 8;
    if (t >= TILES) return;

    int r1 = t * 16 + (lane >> 2);
    int r2 = r1 + 8;
    int c0 = s * 16 + (lane & 3) * 2;

    float2 x00 = make_float2(0.f, 0.f), x10 = x00, x01 = x00, x11 = x00;
    if (r1 < n) {
        x00 = *(const float2*)&h[(size_t)r1 * HD + c0];
        x01 = *(const float2*)&h[(size_t)r1 * HD + c0 + 8];
    }
    if (r2 < n) {
        x10 = *(const float2*)&h[(size_t)r2 * HD + c0];
        x11 = *(const float2*)&h[(size_t)r2 * HD + c0 + 8];
    }

    uint4 hi, lo;
    split2(x00.x, x00.y, hi.x, lo.x);
    split2(x10.x, x10.y, hi.y, lo.y);
    split2(x01.x, x01.y, hi.z, lo.z);
    split2(x11.x, x11.y, hi.w, lo.w);

    g_Afrag_hi[idx] = hi;
    g_Afrag_lo[idx] = lo;
}

// ---------------------------------------------------------------------------
// prep_B: W (fp32 [k=128][n=128], row-major) -> bf16 fragments.
// B fragment (col-major 16x8): b0: (k = (l&3)*2 +{0,1}, n = l>>2); b1: k+8.
// One thread per (mat, kstep, ntile, lane). 12288 threads total.
// ---------------------------------------------------------------------------
__global__ void prep_B(const float* __restrict__ Wq, const float* __restrict__ Wk,
                       const float* __restrict__ Wv) {
    int idx = blockIdx.x * blockDim.x + threadIdx.x;
    if (idx >= 3 * KSTEPS * 16 * 32) return;
    int lane = idx & 31;
    int j    = (idx >> 5) & 15;
    int s    = (idx >> 9) & 7;
    int m    = idx >> 12;

    const float* W = (m == 0) ? Wq : (m == 1) ? Wk : Wv;
    int nn = j * 8 + (lane >> 2);
    int k0 = s * 16 + (lane & 3) * 2;

    float w00 = W[(size_t)(k0 + 0) * HD + nn];
    float w01 = W[(size_t)(k0 + 1) * HD + nn];
    float w10 = W[(size_t)(k0 + 8) * HD + nn];
    float w11 = W[(size_t)(k0 + 9) * HD + nn];

    uint4 v;
    uint32_t lo0, lo1;
    split2(w00, w01, v.x, lo0);
    split2(w10, w11, v.y, lo1);
    v.z = lo0;
    v.w = lo1;
    g_Bfrag[idx] = v;
}

// ---------------------------------------------------------------------------
// qkv_mma: out_m = h @ W_m + b_m on HMMA (bf16 3-term split, effective K=384).
// grid (TILES/4, 3), 128 threads. Warp w computes rows [tile*16, tile*16+16).
// B fragments staged per-kstep through 8KB smem.
// m==0 -> g_Q fp32; m==1 -> g_Kh fp16; m==2 -> g_Vh fp16.
// ---------------------------------------------------------------------------
__global__ void __launch_bounds__(128)
qkv_mma(const float* __restrict__ bq, const float* __restrict__ bk,
        const float* __restrict__ bv) {
    __shared__ uint4 sB[16 * 32];      // 8KB: this kstep's B fragments
    __shared__ float sbias[128];

    const int tid  = threadIdx.x;
    const int wid  = tid >> 5;
    const int lane = tid & 31;
    const int m    = blockIdx.y;
    const int tile = blockIdx.x * 4 + wid;

    const float* bias = (m == 0) ? bq : (m == 1) ? bk : bv;
    sbias[tid] = bias[tid];

    float acc[16][4];
#pragma unroll
    for (int j = 0; j < 16; j++)
#pragma unroll
        for (int r = 0; r < 4; r++) acc[j][r] = 0.f;

    const uint4* Ah = &g_Afrag_hi[(size_t)tile * KSTEPS * 32 + lane];
    const uint4* Al = &g_Afrag_lo[(size_t)tile * KSTEPS * 32 + lane];
    const uint4* Bg = &g_Bfrag[(size_t)m * KSTEPS * 16 * 32];

    for (int s = 0; s < KSTEPS; s++) {
        __syncthreads();
#pragma unroll
        for (int i = 0; i < 4; i++)
            sB[tid + i * 128] = Bg[s * 512 + tid + i * 128];
        __syncthreads();

        const uint4 ah = Ah[s * 32];
        const uint4 al = Al[s * 32];

#pragma unroll
        for (int j = 0; j < 16; j++) {
            const uint4 b = sB[j * 32 + lane];
            MMA16816(acc[j], ah.x, ah.y, ah.z, ah.w, b.x, b.y);  // hi*hi
            MMA16816(acc[j], al.x, al.y, al.z, al.w, b.x, b.y);  // lo*hi
            MMA16816(acc[j], ah.x, ah.y, ah.z, ah.w, b.z, b.w);  // hi*lo
        }
    }

    // Epilogue: c0,c1 -> (r1, c0..c0+1); c2,c3 -> (r1+8). Padded rows are safe.
    const int r1 = tile * 16 + (lane >> 2);
    const int r2 = r1 + 8;

#pragma unroll
    for (int j = 0; j < 16; j++) {
        int c0 = j * 8 + (lane & 3) * 2;
        float o0 = acc[j][0] + sbias[c0];
        float o1 = acc[j][1] + sbias[c0 + 1];
        float o2 = acc[j][2] + sbias[c0];
        float o3 = acc[j][3] + sbias[c0 + 1];
        if (m == 0) {
            *(float2*)&g_Q[(size_t)r1 * HD + c0] = make_float2(o0, o1);
            *(float2*)&g_Q[(size_t)r2 * HD + c0] = make_float2(o2, o3);
        } else if (m == 1) {
            *(__half2*)&g_Kh[(size_t)r1 * HD + c0] = __floats2half2_rn(o0, o1);
            *(__half2*)&g_Kh[(size_t)r2 * HD + c0] = __floats2half2_rn(o2, o3);
        } else {
            *(__half2*)&g_Vh[(size_t)r1 * HD + c0] = __floats2half2_rn(o0, o1);
            *(__half2*)&g_Vh[(size_t)r2 * HD + c0] = __floats2half2_rn(o2, o3);
        }
    }
}

// ---------------------------------------------------------------------------
// Counting sort by dst: zero -> histogram -> scan -> scatter
// ---------------------------------------------------------------------------
__global__ void zero_cnt_kernel(int n) {
    int i = blockIdx.x * blockDim.x + threadIdx.x;
    if (i < n) g_cnt[i] = 0;
}

__global__ void hist_kernel(const int* __restrict__ dst, int E) {
    for (int i = blockIdx.x * blockDim.x + threadIdx.x; i < E;
         i += gridDim.x * blockDim.x)
        atomicAdd(&g_cnt[dst[i]], 1);
}

#define SCAN_T 1024
__global__ void scan_kernel(int n) {
    __shared__ int ssum[SCAN_T];
    const int tid = threadIdx.x;
    const int per = (n + SCAN_T - 1) / SCAN_T;
    const int start = tid * per;
    const int end   = min(start + per, n);

    int s = 0;
    for (int i = start; i < end; i++) s += g_cnt[i];
    ssum[tid] = s;
    __syncthreads();

    for (int off = 1; off < SCAN_T; off <<= 1) {
        int t = (tid >= off) ? ssum[tid - off] : 0;
        __syncthreads();
        ssum[tid] += t;
        __syncthreads();
    }

    int run = ssum[tid] - s;
    for (int i = start; i < end; i++) {
        int c = g_cnt[i];
        g_off[i] = run;
        g_pos[i] = run;
        run += c;
    }
    if (tid == SCAN_T - 1) g_off[n] = run;
}

__global__ void scatter_kernel(const int* __restrict__ src,
                               const int* __restrict__ dst, int E) {
    for (int i = blockIdx.x * blockDim.x + threadIdx.x; i < E;
         i += gridDim.x * blockDim.x) {
        int d = dst[i];
        int p = atomicAdd(&g_pos[d], 1);
        g_esrc[p] = src[i];
    }
}

// ---------------------------------------------------------------------------
// Gather: one warp per destination node. Q fp32 in regs; K/V fp16 (halved L2
// traffic). Accumulate and normalize in registers, no atomics.
// ---------------------------------------------------------------------------
__global__ void gather_kernel(float* __restrict__ out, int n) {
    int node = (blockIdx.x * blockDim.x + threadIdx.x) >> 5;
    if (node >= n) return;
    const int lane = threadIdx.x & 31;

    const float4 q4 = *(const float4*)&g_Q[(size_t)node * HD + lane * 4];

    float ax = 0.f, ay = 0.f, az = 0.f, aw = 0.f;
    float zacc = 0.f;

    const int beg  = g_off[node];
    const int endo = g_off[node + 1];

    for (int ebase = beg; ebase < endo; ebase += 32) {
        int eidx = ebase + lane;
        int my_s = (eidx < endo) ? g_esrc[eidx] : 0;
        int cnt = endo - ebase;
        if (cnt > 32) cnt = 32;

        for (int j = 0; j < cnt; j++) {
            int s = __shfl_sync(0xffffffffu, my_s, j);

            uint2 ku = *(const uint2*)(g_Kh + (size_t)s * HD + lane * 4);
            uint2 vu = *(const uint2*)(g_Vh + (size_t)s * HD + lane * 4);

            float2 k01 = __half22float2(*reinterpret_cast<__half2*>(&ku.x));
            float2 k23 = __half22float2(*reinterpret_cast<__half2*>(&ku.y));

            float p = k01.x * q4.x + k01.y * q4.y + k23.x * q4.z + k23.y * q4.w;
            p += __shfl_xor_sync(0xffffffffu, p, 1);
            p += __shfl_xor_sync(0xffffffffu, p, 2);

            float sc = __expf(fminf(fmaxf(p * 0.25f, -5.0f), 5.0f));

            float2 v01 = __half22float2(*reinterpret_cast<__half2*>(&vu.x));
            float2 v23 = __half22float2(*reinterpret_cast<__half2*>(&vu.y));

            ax += v01.x * sc;
            ay += v01.y * sc;
            az += v23.x * sc;
            aw += v23.y * sc;
            zacc += sc;
        }
    }

    float inv = 1.0f / (zacc + 1e-6f);
    float4 o = make_float4(ax * inv, ay * inv, az * inv, aw * inv);
    *(float4*)&out[(size_t)node * HD + lane * 4] = o;
}

// ---------------------------------------------------------------------------
extern "C" void kernel_launch(void* const* d_in, const int* in_sizes, int n_in,
                              void* d_out, int out_size) {
    const float* h  = (const float*)d_in[0];
    const float* Wq = (const float*)d_in[1];
    const float* bq = (const float*)d_in[2];
    const float* Wk = (const float*)d_in[3];
    const float* bk = (const float*)d_in[4];
    const float* Wv = (const float*)d_in[5];
    const float* bv = (const float*)d_in[6];
    const int*  src = (const int*)d_in[7];
    const int*  dst = (const int*)d_in[8];
    float* out = (float*)d_out;

    const int n = in_sizes[0] / HD;
    const int E = in_sizes[7];

    // CSR sort by dst
    zero_cnt_kernel<<<(n + 255) / 256, 256>>>(n);
    hist_kernel<<<2368, 256>>>(dst, E);
    scan_kernel<<<1, SCAN_T>>>(n);
    scatter_kernel<<<2368, 256>>>(src, dst, E);

    // QKV projections on HMMA (bf16 3-term split)
    prep_A<<<TILES, 256>>>(h, n);             // 3128 blocks x 256 = exact cover
    prep_B<<<48, 256>>>(Wq, Wk, Wv);
    dim3 gg(TILES / 4, 3);
    qkv_mma<<<gg, 128>>>(bq, bk, bv);

    // Gather + normalize (one warp per node)
    gather_kernel<<<(n * 32 + 255) / 256, 256>>>(out, n);
}

// round 5
// speedup vs baseline: 1.6692x; 1.1081x over previous
#include <cuda_runtime.h>
#include <cuda_bf16.h>
#include <cuda_fp16.h>
#include <math.h>
#include <cstdint>

#define HD       128
#define MAXN     50000
#define MAXN_PAD 50048            // 782 * 64
#define MAXE     1600000
#define TILES    (MAXN_PAD / 16)  // 3128 (16-row warp tiles)
#define KSTEPS   8

// ---------------------------------------------------------------------------
// Device scratch (allocation-free per harness rules)
// ---------------------------------------------------------------------------
__device__ float  g_Q [MAXN_PAD * HD];
__device__ __half g_Kh[MAXN_PAD * HD];
__device__ __half g_Vh[MAXN_PAD * HD];

// Fragment-major A (bf16 hi/lo): [tile][kstep][lane] -> uint4 (4 b32 = 8 bf16)
__device__ uint4 g_Afrag_hi[TILES * KSTEPS * 32];
__device__ uint4 g_Afrag_lo[TILES * KSTEPS * 32];
// Fragment-major B: [mat][kstep][ntile][lane] -> uint4 {b0hi,b1hi,b0lo,b1lo}
__device__ uint4 g_Bfrag[3 * KSTEPS * 16 * 32];

// CSR sort scratch
__device__ int g_cnt[MAXN];
__device__ int g_off[MAXN + 1];
__device__ int g_pos[MAXN];
__device__ int g_esrc[MAXE];

// ---------------------------------------------------------------------------
// Helpers
// ---------------------------------------------------------------------------
__device__ __forceinline__ void split2(float x, float y, uint32_t& hi, uint32_t& lo) {
    __nv_bfloat16 hx = __float2bfloat16(x);
    __nv_bfloat16 hy = __float2bfloat16(y);
    __nv_bfloat16 lx = __float2bfloat16(x - __bfloat162float(hx));
    __nv_bfloat16 ly = __float2bfloat16(y - __bfloat162float(hy));
    __nv_bfloat162 H(hx, hy), L(lx, ly);
    hi = *(uint32_t*)&H;
    lo = *(uint32_t*)&L;
}

#define MMA16816(c, a0, a1, a2, a3, b0, b1)                                  \
    asm volatile(                                                            \
        "mma.sync.aligned.m16n8k16.row.col.f32.bf16.bf16.f32 "              \
        "{%0,%1,%2,%3}, {%4,%5,%6,%7}, {%8,%9}, {%0,%1,%2,%3};"             \
        : "+f"((c)[0]), "+f"((c)[1]), "+f"((c)[2]), "+f"((c)[3])             \
        : "r"(a0), "r"(a1), "r"(a2), "r"(a3), "r"(b0), "r"(b1))

// ---------------------------------------------------------------------------
// prep_A: h (fp32) -> bf16 hi/lo fragments. One thread per (tile, kstep, lane).
// ---------------------------------------------------------------------------
__global__ void prep_A(const float* __restrict__ h, int n) {
    int idx = blockIdx.x * blockDim.x + threadIdx.x;
    int lane = idx & 31;
    int s    = (idx >> 5) & 7;
    int t    = idx >> 8;
    if (t >= TILES) return;

    int r1 = t * 16 + (lane >> 2);
    int r2 = r1 + 8;
    int c0 = s * 16 + (lane & 3) * 2;

    float2 x00 = make_float2(0.f, 0.f), x10 = x00, x01 = x00, x11 = x00;
    if (r1 < n) {
        x00 = *(const float2*)&h[(size_t)r1 * HD + c0];
        x01 = *(const float2*)&h[(size_t)r1 * HD + c0 + 8];
    }
    if (r2 < n) {
        x10 = *(const float2*)&h[(size_t)r2 * HD + c0];
        x11 = *(const float2*)&h[(size_t)r2 * HD + c0 + 8];
    }

    uint4 hi, lo;
    split2(x00.x, x00.y, hi.x, lo.x);
    split2(x10.x, x10.y, hi.y, lo.y);
    split2(x01.x, x01.y, hi.z, lo.z);
    split2(x11.x, x11.y, hi.w, lo.w);

    g_Afrag_hi[idx] = hi;
    g_Afrag_lo[idx] = lo;
}

// ---------------------------------------------------------------------------
// prep_B: W (fp32 [k=128][n=128], row-major) -> bf16 fragments.
// ---------------------------------------------------------------------------
__global__ void prep_B(const float* __restrict__ Wq, const float* __restrict__ Wk,
                       const float* __restrict__ Wv) {
    int idx = blockIdx.x * blockDim.x + threadIdx.x;
    if (idx >= 3 * KSTEPS * 16 * 32) return;
    int lane = idx & 31;
    int j    = (idx >> 5) & 15;
    int s    = (idx >> 9) & 7;
    int m    = idx >> 12;

    const float* W = (m == 0) ? Wq : (m == 1) ? Wk : Wv;
    int nn = j * 8 + (lane >> 2);
    int k0 = s * 16 + (lane & 3) * 2;

    float w00 = W[(size_t)(k0 + 0) * HD + nn];
    float w01 = W[(size_t)(k0 + 1) * HD + nn];
    float w10 = W[(size_t)(k0 + 8) * HD + nn];
    float w11 = W[(size_t)(k0 + 9) * HD + nn];

    uint4 v;
    uint32_t lo0, lo1;
    split2(w00, w01, v.x, lo0);
    split2(w10, w11, v.y, lo1);
    v.z = lo0;
    v.w = lo1;
    g_Bfrag[idx] = v;
}

// ---------------------------------------------------------------------------
// qkv_mma: out_m = h @ W_m + b_m on HMMA (bf16 3-term split, effective K=384).
// ---------------------------------------------------------------------------
__global__ void __launch_bounds__(128)
qkv_mma(const float* __restrict__ bq, const float* __restrict__ bk,
        const float* __restrict__ bv) {
    __shared__ uint4 sB[16 * 32];
    __shared__ float sbias[128];

    const int tid  = threadIdx.x;
    const int wid  = tid >> 5;
    const int lane = tid & 31;
    const int m    = blockIdx.y;
    const int tile = blockIdx.x * 4 + wid;

    const float* bias = (m == 0) ? bq : (m == 1) ? bk : bv;
    sbias[tid] = bias[tid];

    float acc[16][4];
#pragma unroll
    for (int j = 0; j < 16; j++)
#pragma unroll
        for (int r = 0; r < 4; r++) acc[j][r] = 0.f;

    const uint4* Ah = &g_Afrag_hi[(size_t)tile * KSTEPS * 32 + lane];
    const uint4* Al = &g_Afrag_lo[(size_t)tile * KSTEPS * 32 + lane];
    const uint4* Bg = &g_Bfrag[(size_t)m * KSTEPS * 16 * 32];

    for (int s = 0; s < KSTEPS; s++) {
        __syncthreads();
#pragma unroll
        for (int i = 0; i < 4; i++)
            sB[tid + i * 128] = Bg[s * 512 + tid + i * 128];
        __syncthreads();

        const uint4 ah = Ah[s * 32];
        const uint4 al = Al[s * 32];

#pragma unroll
        for (int j = 0; j < 16; j++) {
            const uint4 b = sB[j * 32 + lane];
            MMA16816(acc[j], ah.x, ah.y, ah.z, ah.w, b.x, b.y);  // hi*hi
            MMA16816(acc[j], al.x, al.y, al.z, al.w, b.x, b.y);  // lo*hi
            MMA16816(acc[j], ah.x, ah.y, ah.z, ah.w, b.z, b.w);  // hi*lo
        }
    }

    const int r1 = tile * 16 + (lane >> 2);
    const int r2 = r1 + 8;

#pragma unroll
    for (int j = 0; j < 16; j++) {
        int c0 = j * 8 + (lane & 3) * 2;
        float o0 = acc[j][0] + sbias[c0];
        float o1 = acc[j][1] + sbias[c0 + 1];
        float o2 = acc[j][2] + sbias[c0];
        float o3 = acc[j][3] + sbias[c0 + 1];
        if (m == 0) {
            *(float2*)&g_Q[(size_t)r1 * HD + c0] = make_float2(o0, o1);
            *(float2*)&g_Q[(size_t)r2 * HD + c0] = make_float2(o2, o3);
        } else if (m == 1) {
            *(__half2*)&g_Kh[(size_t)r1 * HD + c0] = __floats2half2_rn(o0, o1);
            *(__half2*)&g_Kh[(size_t)r2 * HD + c0] = __floats2half2_rn(o2, o3);
        } else {
            *(__half2*)&g_Vh[(size_t)r1 * HD + c0] = __floats2half2_rn(o0, o1);
            *(__half2*)&g_Vh[(size_t)r2 * HD + c0] = __floats2half2_rn(o2, o3);
        }
    }
}

// ---------------------------------------------------------------------------
// Counting sort by dst
// ---------------------------------------------------------------------------
__global__ void zero_cnt_kernel(int n) {
    int i = blockIdx.x * blockDim.x + threadIdx.x;
    if (i < n) g_cnt[i] = 0;
}

__global__ void hist_kernel(const int* __restrict__ dst, int E) {
    int E4 = E >> 2;
    for (int i = blockIdx.x * blockDim.x + threadIdx.x; i < E4;
         i += gridDim.x * blockDim.x) {
        int4 d = ((const int4*)dst)[i];
        atomicAdd(&g_cnt[d.x], 1);
        atomicAdd(&g_cnt[d.y], 1);
        atomicAdd(&g_cnt[d.z], 1);
        atomicAdd(&g_cnt[d.w], 1);
    }
    // tail
    int i = E4 * 4 + blockIdx.x * blockDim.x + threadIdx.x;
    if (i < E) atomicAdd(&g_cnt[dst[i]], 1);
}

#define SCAN_T 1024
__global__ void scan_kernel(int n) {
    __shared__ int ssum[SCAN_T];
    const int tid = threadIdx.x;
    const int per = (n + SCAN_T - 1) / SCAN_T;
    const int start = tid * per;
    const int end   = min(start + per, n);

    int s = 0;
    for (int i = start; i < end; i++) s += g_cnt[i];
    ssum[tid] = s;
    __syncthreads();

    for (int off = 1; off < SCAN_T; off <<= 1) {
        int t = (tid >= off) ? ssum[tid - off] : 0;
        __syncthreads();
        ssum[tid] += t;
        __syncthreads();
    }

    int run = ssum[tid] - s;
    for (int i = start; i < end; i++) {
        int c = g_cnt[i];
        g_off[i] = run;
        g_pos[i] = run;
        run += c;
    }
    if (tid == SCAN_T - 1) g_off[n] = run;
}

__global__ void scatter_kernel(const int* __restrict__ src,
                               const int* __restrict__ dst, int E) {
    for (int i = blockIdx.x * blockDim.x + threadIdx.x; i < E;
         i += gridDim.x * blockDim.x) {
        int d = dst[i];
        int p = atomicAdd(&g_pos[d], 1);
        g_esrc[p] = src[i];
    }
}

// ---------------------------------------------------------------------------
// Gather: one warp per destination node; 8-edge software-pipelined batches.
// Load phase issues 16 independent LDG.64 before compute phase -> MLP ~16.
// ---------------------------------------------------------------------------
__global__ void gather_kernel(float* __restrict__ out, int n) {
    int node = (blockIdx.x * blockDim.x + threadIdx.x) >> 5;
    if (node >= n) return;
    const int lane = threadIdx.x & 31;
    const size_t loff = (size_t)lane * 4;

    const float4 q4 = *(const float4*)&g_Q[(size_t)node * HD + loff];

    float ax = 0.f, ay = 0.f, az = 0.f, aw = 0.f;
    float zacc = 0.f;

    const int beg  = g_off[node];
    const int endo = g_off[node + 1];

    for (int ebase = beg; ebase < endo; ebase += 32) {
        int eidx = ebase + lane;
        int my_s = (eidx < endo) ? g_esrc[eidx] : 0;
        int cnt = endo - ebase;
        if (cnt > 32) cnt = 32;

        int j = 0;
        for (; j + 8 <= cnt; j += 8) {
            uint2 ks[8], vs[8];
#pragma unroll
            for (int u = 0; u < 8; u++) {
                int s = __shfl_sync(0xffffffffu, my_s, j + u);
                const size_t base = (size_t)s * HD + loff;
                ks[u] = *(const uint2*)(g_Kh + base);
                vs[u] = *(const uint2*)(g_Vh + base);
            }
#pragma unroll
            for (int u = 0; u < 8; u++) {
                float2 k01 = __half22float2(*reinterpret_cast<__half2*>(&ks[u].x));
                float2 k23 = __half22float2(*reinterpret_cast<__half2*>(&ks[u].y));

                float p = k01.x * q4.x + k01.y * q4.y + k23.x * q4.z + k23.y * q4.w;
                p += __shfl_xor_sync(0xffffffffu, p, 1);
                p += __shfl_xor_sync(0xffffffffu, p, 2);

                float sc = __expf(fminf(fmaxf(p * 0.25f, -5.0f), 5.0f));

                float2 v01 = __half22float2(*reinterpret_cast<__half2*>(&vs[u].x));
                float2 v23 = __half22float2(*reinterpret_cast<__half2*>(&vs[u].y));

                ax += v01.x * sc;
                ay += v01.y * sc;
                az += v23.x * sc;
                aw += v23.y * sc;
                zacc += sc;
            }
        }
        for (; j < cnt; j++) {
            int s = __shfl_sync(0xffffffffu, my_s, j);
            const size_t base = (size_t)s * HD + loff;
            uint2 ku = *(const uint2*)(g_Kh + base);
            uint2 vu = *(const uint2*)(g_Vh + base);

            float2 k01 = __half22float2(*reinterpret_cast<__half2*>(&ku.x));
            float2 k23 = __half22float2(*reinterpret_cast<__half2*>(&ku.y));

            float p = k01.x * q4.x + k01.y * q4.y + k23.x * q4.z + k23.y * q4.w;
            p += __shfl_xor_sync(0xffffffffu, p, 1);
            p += __shfl_xor_sync(0xffffffffu, p, 2);

            float sc = __expf(fminf(fmaxf(p * 0.25f, -5.0f), 5.0f));

            float2 v01 = __half22float2(*reinterpret_cast<__half2*>(&vu.x));
            float2 v23 = __half22float2(*reinterpret_cast<__half2*>(&vu.y));

            ax += v01.x * sc;
            ay += v01.y * sc;
            az += v23.x * sc;
            aw += v23.y * sc;
            zacc += sc;
        }
    }

    float inv = 1.0f / (zacc + 1e-6f);
    float4 o = make_float4(ax * inv, ay * inv, az * inv, aw * inv);
    *(float4*)&out[(size_t)node * HD + loff] = o;
}

// ---------------------------------------------------------------------------
extern "C" void kernel_launch(void* const* d_in, const int* in_sizes, int n_in,
                              void* d_out, int out_size) {
    const float* h  = (const float*)d_in[0];
    const float* Wq = (const float*)d_in[1];
    const float* bq = (const float*)d_in[2];
    const float* Wk = (const float*)d_in[3];
    const float* bk = (const float*)d_in[4];
    const float* Wv = (const float*)d_in[5];
    const float* bv = (const float*)d_in[6];
    const int*  src = (const int*)d_in[7];
    const int*  dst = (const int*)d_in[8];
    float* out = (float*)d_out;

    const int n = in_sizes[0] / HD;
    const int E = in_sizes[7];

    // CSR sort by dst
    zero_cnt_kernel<<<(n + 255) / 256, 256>>>(n);
    hist_kernel<<<1184, 256>>>(dst, E);
    scan_kernel<<<1, SCAN_T>>>(n);
    scatter_kernel<<<2368, 256>>>(src, dst, E);

    // QKV projections on HMMA (bf16 3-term split)
    prep_A<<<TILES, 256>>>(h, n);
    prep_B<<<48, 256>>>(Wq, Wk, Wv);
    dim3 gg(TILES / 4, 3);
    qkv_mma<<<gg, 128>>>(bq, bk, bv);

    // Gather + normalize (one warp per node)
    gather_kernel<<<(n * 32 + 255) / 256, 256>>>(out, n);
}

// round 6
// speedup vs baseline: 1.7636x; 1.0565x over previous
#include <cuda_runtime.h>
#include <cuda_bf16.h>
#include <cuda_fp16.h>
#include <math.h>
#include <cstdint>

#define HD       128
#define MAXN     50000
#define MAXN_PAD 50048            // 782 * 64
#define MAXE     1600000
#define TILES    (MAXN_PAD / 16)  // 3128 (16-row warp tiles)
#define KSTEPS   8

// ---------------------------------------------------------------------------
// Device scratch (allocation-free per harness rules)
// ---------------------------------------------------------------------------
__device__ float g_Q[MAXN_PAD * HD];
// Interleaved K/V, fp16: g_KV[node*32 + l] = {K2(4l),K2(4l+2),V2(4l),V2(4l+2)}
__device__ uint4 g_KV[MAXN_PAD * 32];

// Fragment-major A (bf16 hi/lo): [tile][kstep][lane] -> uint4 (4 b32 = 8 bf16)
__device__ uint4 g_Afrag_hi[TILES * KSTEPS * 32];
__device__ uint4 g_Afrag_lo[TILES * KSTEPS * 32];
// Fragment-major B: [mat][kstep][ntile][lane] -> uint4 {b0hi,b1hi,b0lo,b1lo}
__device__ uint4 g_Bfrag[3 * KSTEPS * 16 * 32];

// CSR sort scratch
__device__ int g_cnt[MAXN];
__device__ int g_off[MAXN + 1];
__device__ int g_pos[MAXN];
__device__ int g_esrc[MAXE];

// ---------------------------------------------------------------------------
// Helpers
// ---------------------------------------------------------------------------
__device__ __forceinline__ void split2(float x, float y, uint32_t& hi, uint32_t& lo) {
    __nv_bfloat16 hx = __float2bfloat16(x);
    __nv_bfloat16 hy = __float2bfloat16(y);
    __nv_bfloat16 lx = __float2bfloat16(x - __bfloat162float(hx));
    __nv_bfloat16 ly = __float2bfloat16(y - __bfloat162float(hy));
    __nv_bfloat162 H(hx, hy), L(lx, ly);
    hi = *(uint32_t*)&H;
    lo = *(uint32_t*)&L;
}

#define MMA16816(c, a0, a1, a2, a3, b0, b1)                                  \
    asm volatile(                                                            \
        "mma.sync.aligned.m16n8k16.row.col.f32.bf16.bf16.f32 "              \
        "{%0,%1,%2,%3}, {%4,%5,%6,%7}, {%8,%9}, {%0,%1,%2,%3};"             \
        : "+f"((c)[0]), "+f"((c)[1]), "+f"((c)[2]), "+f"((c)[3])             \
        : "r"(a0), "r"(a1), "r"(a2), "r"(a3), "r"(b0), "r"(b1))

// ---------------------------------------------------------------------------
// prep_A: h (fp32) -> bf16 hi/lo fragments. One thread per (tile, kstep, lane).
// ---------------------------------------------------------------------------
__global__ void prep_A(const float* __restrict__ h, int n) {
    int idx = blockIdx.x * blockDim.x + threadIdx.x;
    int lane = idx & 31;
    int s    = (idx >> 5) & 7;
    int t    = idx >> 8;
    if (t >= TILES) return;

    int r1 = t * 16 + (lane >> 2);
    int r2 = r1 + 8;
    int c0 = s * 16 + (lane & 3) * 2;

    float2 x00 = make_float2(0.f, 0.f), x10 = x00, x01 = x00, x11 = x00;
    if (r1 < n) {
        x00 = *(const float2*)&h[(size_t)r1 * HD + c0];
        x01 = *(const float2*)&h[(size_t)r1 * HD + c0 + 8];
    }
    if (r2 < n) {
        x10 = *(const float2*)&h[(size_t)r2 * HD + c0];
        x11 = *(const float2*)&h[(size_t)r2 * HD + c0 + 8];
    }

    uint4 hi, lo;
    split2(x00.x, x00.y, hi.x, lo.x);
    split2(x10.x, x10.y, hi.y, lo.y);
    split2(x01.x, x01.y, hi.z, lo.z);
    split2(x11.x, x11.y, hi.w, lo.w);

    g_Afrag_hi[idx] = hi;
    g_Afrag_lo[idx] = lo;
}

// ---------------------------------------------------------------------------
// prep_B: W (fp32 [k=128][n=128], row-major) -> bf16 fragments.
// ---------------------------------------------------------------------------
__global__ void prep_B(const float* __restrict__ Wq, const float* __restrict__ Wk,
                       const float* __restrict__ Wv) {
    int idx = blockIdx.x * blockDim.x + threadIdx.x;
    if (idx >= 3 * KSTEPS * 16 * 32) return;
    int lane = idx & 31;
    int j    = (idx >> 5) & 15;
    int s    = (idx >> 9) & 7;
    int m    = idx >> 12;

    const float* W = (m == 0) ? Wq : (m == 1) ? Wk : Wv;
    int nn = j * 8 + (lane >> 2);
    int k0 = s * 16 + (lane & 3) * 2;

    float w00 = W[(size_t)(k0 + 0) * HD + nn];
    float w01 = W[(size_t)(k0 + 1) * HD + nn];
    float w10 = W[(size_t)(k0 + 8) * HD + nn];
    float w11 = W[(size_t)(k0 + 9) * HD + nn];

    uint4 v;
    uint32_t lo0, lo1;
    split2(w00, w01, v.x, lo0);
    split2(w10, w11, v.y, lo1);
    v.z = lo0;
    v.w = lo1;
    g_Bfrag[idx] = v;
}

// ---------------------------------------------------------------------------
// qkv_mma: computes Q, K, V in ONE kernel (A fragments reused from registers).
// grid = TILES/4, 128 threads; warp w owns tile = blockIdx.x*4 + w.
// j split into two halves (jh) to keep acc at 3*8*4 = 96 regs.
// B fragments via __ldg (192KB total, L1/L2-resident, shared across warps).
// ---------------------------------------------------------------------------
__global__ void __launch_bounds__(128)
qkv_mma(const float* __restrict__ bq, const float* __restrict__ bk,
        const float* __restrict__ bv) {
    __shared__ float sbias[3][128];

    const int tid  = threadIdx.x;
    const int wid  = tid >> 5;
    const int lane = tid & 31;
    const int tile = blockIdx.x * 4 + wid;

    sbias[0][tid] = bq[tid];
    sbias[1][tid] = bk[tid];
    sbias[2][tid] = bv[tid];
    __syncthreads();

    const uint4* Ah = &g_Afrag_hi[(size_t)tile * KSTEPS * 32 + lane];
    const uint4* Al = &g_Afrag_lo[(size_t)tile * KSTEPS * 32 + lane];

    const int r1 = tile * 16 + (lane >> 2);
    const int r2 = r1 + 8;

    for (int jh = 0; jh < 2; jh++) {
        float acc[3][8][4];
#pragma unroll
        for (int m = 0; m < 3; m++)
#pragma unroll
            for (int j = 0; j < 8; j++)
#pragma unroll
                for (int r = 0; r < 4; r++) acc[m][j][r] = 0.f;

        for (int s = 0; s < KSTEPS; s++) {
            const uint4 ah = Ah[s * 32];
            const uint4 al = Al[s * 32];
#pragma unroll
            for (int m = 0; m < 3; m++) {
#pragma unroll
                for (int j = 0; j < 8; j++) {
                    const uint4 b = __ldg(&g_Bfrag[(size_t)m * (KSTEPS * 512) +
                                                   s * 512 + (jh * 8 + j) * 32 + lane]);
                    MMA16816(acc[m][j], ah.x, ah.y, ah.z, ah.w, b.x, b.y);  // hi*hi
                    MMA16816(acc[m][j], al.x, al.y, al.z, al.w, b.x, b.y);  // lo*hi
                    MMA16816(acc[m][j], ah.x, ah.y, ah.z, ah.w, b.z, b.w);  // hi*lo
                }
            }
        }

        // Epilogue for this jh half.
#pragma unroll
        for (int j = 0; j < 8; j++) {
            const int c0 = (jh * 8 + j) * 8 + (lane & 3) * 2;
            const int kvlane = c0 >> 2;           // gather lane that owns col c0
            const int pi     = (c0 >> 1) & 1;     // half2 slot within uint4 comp pair

            // Q (fp32)
            {
                float o0 = acc[0][j][0] + sbias[0][c0];
                float o1 = acc[0][j][1] + sbias[0][c0 + 1];
                float o2 = acc[0][j][2] + sbias[0][c0];
                float o3 = acc[0][j][3] + sbias[0][c0 + 1];
                *(float2*)&g_Q[(size_t)r1 * HD + c0] = make_float2(o0, o1);
                *(float2*)&g_Q[(size_t)r2 * HD + c0] = make_float2(o2, o3);
            }
            // K (fp16 -> g_KV components 0/1)
            {
                float o0 = acc[1][j][0] + sbias[1][c0];
                float o1 = acc[1][j][1] + sbias[1][c0 + 1];
                float o2 = acc[1][j][2] + sbias[1][c0];
                float o3 = acc[1][j][3] + sbias[1][c0 + 1];
                __half2 p1 = __floats2half2_rn(o0, o1);
                __half2 p2 = __floats2half2_rn(o2, o3);
                ((uint32_t*)&g_KV[(size_t)r1 * 32 + kvlane])[pi] = *(uint32_t*)&p1;
                ((uint32_t*)&g_KV[(size_t)r2 * 32 + kvlane])[pi] = *(uint32_t*)&p2;
            }
            // V (fp16 -> g_KV components 2/3)
            {
                float o0 = acc[2][j][0] + sbias[2][c0];
                float o1 = acc[2][j][1] + sbias[2][c0 + 1];
                float o2 = acc[2][j][2] + sbias[2][c0];
                float o3 = acc[2][j][3] + sbias[2][c0 + 1];
                __half2 p1 = __floats2half2_rn(o0, o1);
                __half2 p2 = __floats2half2_rn(o2, o3);
                ((uint32_t*)&g_KV[(size_t)r1 * 32 + kvlane])[2 + pi] = *(uint32_t*)&p1;
                ((uint32_t*)&g_KV[(size_t)r2 * 32 + kvlane])[2 + pi] = *(uint32_t*)&p2;
            }
        }
    }
}

// ---------------------------------------------------------------------------
// Counting sort by dst
// ---------------------------------------------------------------------------
__global__ void zero_cnt_kernel(int n) {
    int i = blockIdx.x * blockDim.x + threadIdx.x;
    if (i < n) g_cnt[i] = 0;
}

__global__ void hist_kernel(const int* __restrict__ dst, int E) {
    int E4 = E >> 2;
    for (int i = blockIdx.x * blockDim.x + threadIdx.x; i < E4;
         i += gridDim.x * blockDim.x) {
        int4 d = ((const int4*)dst)[i];
        atomicAdd(&g_cnt[d.x], 1);
        atomicAdd(&g_cnt[d.y], 1);
        atomicAdd(&g_cnt[d.z], 1);
        atomicAdd(&g_cnt[d.w], 1);
    }
    int i = E4 * 4 + blockIdx.x * blockDim.x + threadIdx.x;
    if (i < E) atomicAdd(&g_cnt[dst[i]], 1);
}

#define SCAN_T 1024
__global__ void scan_kernel(int n) {
    __shared__ int ssum[SCAN_T];
    const int tid = threadIdx.x;
    const int per = (n + SCAN_T - 1) / SCAN_T;
    const int start = tid * per;
    const int end   = min(start + per, n);

    int s = 0;
    for (int i = start; i < end; i++) s += g_cnt[i];
    ssum[tid] = s;
    __syncthreads();

    for (int off = 1; off < SCAN_T; off <<= 1) {
        int t = (tid >= off) ? ssum[tid - off] : 0;
        __syncthreads();
        ssum[tid] += t;
        __syncthreads();
    }

    int run = ssum[tid] - s;
    for (int i = start; i < end; i++) {
        int c = g_cnt[i];
        g_off[i] = run;
        g_pos[i] = run;
        run += c;
    }
    if (tid == SCAN_T - 1) g_off[n] = run;
}

__global__ void scatter_kernel(const int* __restrict__ src,
                               const int* __restrict__ dst, int E) {
    for (int i = blockIdx.x * blockDim.x + threadIdx.x; i < E;
         i += gridDim.x * blockDim.x) {
        int d = dst[i];
        int p = atomicAdd(&g_pos[d], 1);
        g_esrc[p] = src[i];
    }
}

// ---------------------------------------------------------------------------
// Gather: one warp per destination node; 8-edge software-pipelined batches.
// Per edge per lane: ONE LDG.128 from interleaved g_KV (K+V together).
// ---------------------------------------------------------------------------
__global__ void gather_kernel(float* __restrict__ out, int n) {
    int node = (blockIdx.x * blockDim.x + threadIdx.x) >> 5;
    if (node >= n) return;
    const int lane = threadIdx.x & 31;

    const float4 q4 = *(const float4*)&g_Q[(size_t)node * HD + lane * 4];

    float ax = 0.f, ay = 0.f, az = 0.f, aw = 0.f;
    float zacc = 0.f;

    const int beg  = g_off[node];
    const int endo = g_off[node + 1];

    for (int ebase = beg; ebase < endo; ebase += 32) {
        int eidx = ebase + lane;
        int my_s = (eidx < endo) ? g_esrc[eidx] : 0;
        int cnt = endo - ebase;
        if (cnt > 32) cnt = 32;

        int j = 0;
        for (; j + 8 <= cnt; j += 8) {
            uint4 kv[8];
#pragma unroll
            for (int u = 0; u < 8; u++) {
                int s = __shfl_sync(0xffffffffu, my_s, j + u);
                kv[u] = g_KV[(size_t)s * 32 + lane];
            }
#pragma unroll
            for (int u = 0; u < 8; u++) {
                float2 k01 = __half22float2(*reinterpret_cast<__half2*>(&kv[u].x));
                float2 k23 = __half22float2(*reinterpret_cast<__half2*>(&kv[u].y));

                float p = k01.x * q4.x + k01.y * q4.y + k23.x * q4.z + k23.y * q4.w;
                p += __shfl_xor_sync(0xffffffffu, p, 1);
                p += __shfl_xor_sync(0xffffffffu, p, 2);

                float sc = __expf(fminf(fmaxf(p * 0.25f, -5.0f), 5.0f));

                float2 v01 = __half22float2(*reinterpret_cast<__half2*>(&kv[u].z));
                float2 v23 = __half22float2(*reinterpret_cast<__half2*>(&kv[u].w));

                ax += v01.x * sc;
                ay += v01.y * sc;
                az += v23.x * sc;
                aw += v23.y * sc;
                zacc += sc;
            }
        }
        for (; j < cnt; j++) {
            int s = __shfl_sync(0xffffffffu, my_s, j);
            uint4 kv = g_KV[(size_t)s * 32 + lane];

            float2 k01 = __half22float2(*reinterpret_cast<__half2*>(&kv.x));
            float2 k23 = __half22float2(*reinterpret_cast<__half2*>(&kv.y));

            float p = k01.x * q4.x + k01.y * q4.y + k23.x * q4.z + k23.y * q4.w;
            p += __shfl_xor_sync(0xffffffffu, p, 1);
            p += __shfl_xor_sync(0xffffffffu, p, 2);

            float sc = __expf(fminf(fmaxf(p * 0.25f, -5.0f), 5.0f));

            float2 v01 = __half22float2(*reinterpret_cast<__half2*>(&kv.z));
            float2 v23 = __half22float2(*reinterpret_cast<__half2*>(&kv.w));

            ax += v01.x * sc;
            ay += v01.y * sc;
            az += v23.x * sc;
            aw += v23.y * sc;
            zacc += sc;
        }
    }

    float inv = 1.0f / (zacc + 1e-6f);
    float4 o = make_float4(ax * inv, ay * inv, az * inv, aw * inv);
    *(float4*)&out[(size_t)node * HD + lane * 4] = o;
}

// ---------------------------------------------------------------------------
extern "C" void kernel_launch(void* const* d_in, const int* in_sizes, int n_in,
                              void* d_out, int out_size) {
    const float* h  = (const float*)d_in[0];
    const float* Wq = (const float*)d_in[1];
    const float* bq = (const float*)d_in[2];
    const float* Wk = (const float*)d_in[3];
    const float* bk = (const float*)d_in[4];
    const float* Wv = (const float*)d_in[5];
    const float* bv = (const float*)d_in[6];
    const int*  src = (const int*)d_in[7];
    const int*  dst = (const int*)d_in[8];
    float* out = (float*)d_out;

    const int n = in_sizes[0] / HD;
    const int E = in_sizes[7];

    // CSR sort by dst
    zero_cnt_kernel<<<(n + 255) / 256, 256>>>(n);
    hist_kernel<<<1184, 256>>>(dst, E);
    scan_kernel<<<1, SCAN_T>>>(n);
    scatter_kernel<<<2368, 256>>>(src, dst, E);

    // QKV projections on HMMA (bf16 3-term split), fused Q/K/V
    prep_A<<<TILES, 256>>>(h, n);
    prep_B<<<48, 256>>>(Wq, Wk, Wv);
    qkv_mma<<<TILES / 4, 128>>>(bq, bk, bv);

    // Gather + normalize (one warp per node)
    gather_kernel<<<(n * 32 + 255) / 256, 256>>>(out, n);
}